// round 14
// baseline (speedup 1.0000x reference)
#include <cuda_runtime.h>
#include <cuda_bf16.h>
#include <math.h>
#include <stdint.h>

// Problem constants
#define D_MODEL 1024
#define NUM_HEADS 16
#define D_K 64
#define BATCH 4
#define SEQ 2048
#define M_TOTAL (BATCH * SEQ)   // 8192

// ---------------------------------------------------------------------------
// Scratch (device globals)
// ---------------------------------------------------------------------------
__device__ float g_A[M_TOTAL * D_MODEL];
__device__ int8_t g_x1[M_TOTAL * D_MODEL];
__device__ int8_t g_x0[M_TOTAL * D_MODEL];
__device__ int8_t g_a1[M_TOTAL * D_MODEL];
__device__ int8_t g_a0[M_TOTAL * D_MODEL];
__device__ int8_t g_w1[4][D_MODEL * D_MODEL];
__device__ int8_t g_w0[4][D_MODEL * D_MODEL];
__device__ float  g_sx[M_TOTAL];
__device__ float  g_sa[M_TOTAL];
__device__ float  g_sw[4][D_MODEL];
__device__ __nv_bfloat16 g_qhi[M_TOTAL * D_MODEL];
__device__ __nv_bfloat16 g_qlo[M_TOTAL * D_MODEL];
__device__ __nv_bfloat16 g_khi[M_TOTAL * D_MODEL];
__device__ __nv_bfloat16 g_klo[M_TOTAL * D_MODEL];
__device__ __nv_bfloat16 g_vhi[M_TOTAL * D_MODEL];
__device__ __nv_bfloat16 g_vlo[M_TOTAL * D_MODEL];
__device__ float2 g_cs[SEQ * 32];      // (cos, sin) per (position, pair)

// ---------------------------------------------------------------------------
// PTX helpers
// ---------------------------------------------------------------------------
__device__ __forceinline__ uint32_t smem_u32(const void* p) {
    uint32_t a;
    asm("{ .reg .u64 t; cvta.to.shared.u64 t, %1; cvt.u32.u64 %0, t; }" : "=r"(a) : "l"(p));
    return a;
}
__device__ __forceinline__ void cpasync16(uint32_t dst, const void* src) {
    asm volatile("cp.async.ca.shared.global [%0], [%1], 16;" :: "r"(dst), "l"(src));
}
#define CPASYNC_COMMIT() asm volatile("cp.async.commit_group;" ::: "memory")
#define CPASYNC_WAIT1()  asm volatile("cp.async.wait_group 1;" ::: "memory")

__device__ __forceinline__ void ldm_x4(uint32_t* r, uint32_t addr) {
    asm volatile("ldmatrix.sync.aligned.m8n8.x4.shared.b16 {%0,%1,%2,%3}, [%4];"
        : "=r"(r[0]), "=r"(r[1]), "=r"(r[2]), "=r"(r[3]) : "r"(addr));
}
__device__ __forceinline__ void ldm_x4_t(uint32_t* r, uint32_t addr) {
    asm volatile("ldmatrix.sync.aligned.m8n8.x4.trans.shared.b16 {%0,%1,%2,%3}, [%4];"
        : "=r"(r[0]), "=r"(r[1]), "=r"(r[2]), "=r"(r[3]) : "r"(addr));
}
__device__ __forceinline__ void mma_bf16(float* c, const uint32_t* a, const uint32_t* b) {
    asm volatile("mma.sync.aligned.m16n8k16.row.col.f32.bf16.bf16.f32 "
        "{%0,%1,%2,%3}, {%4,%5,%6,%7}, {%8,%9}, {%0,%1,%2,%3};"
        : "+f"(c[0]), "+f"(c[1]), "+f"(c[2]), "+f"(c[3])
        : "r"(a[0]), "r"(a[1]), "r"(a[2]), "r"(a[3]), "r"(b[0]), "r"(b[1]));
}
__device__ __forceinline__ void mma_s8(int* c, const uint32_t* a, const uint32_t* b) {
    asm volatile("mma.sync.aligned.m16n8k32.row.col.s32.s8.s8.s32 "
        "{%0,%1,%2,%3}, {%4,%5,%6,%7}, {%8,%9}, {%0,%1,%2,%3};"
        : "+r"(c[0]), "+r"(c[1]), "+r"(c[2]), "+r"(c[3])
        : "r"(a[0]), "r"(a[1]), "r"(a[2]), "r"(a[3]), "r"(b[0]), "r"(b[1]));
}
__device__ __forceinline__ void q2limb(float v, float inv, int* l1, int* l0) {
    float t = fminf(fmaxf(rintf(v * inv), -16256.f), 16256.f);
    int a1 = __float2int_rn(t * (1.0f / 128.0f));
    *l1 = a1; *l0 = (int)t - (a1 << 7);
}
__device__ __forceinline__ uint32_t pack_split(float a, float b, uint32_t* lo) {
    __nv_bfloat16 ha = __float2bfloat16(a), hb = __float2bfloat16(b);
    __nv_bfloat16 la = __float2bfloat16(a - __bfloat162float(ha));
    __nv_bfloat16 lb = __float2bfloat16(b - __bfloat162float(hb));
    *lo = ((uint32_t)__bfloat16_as_ushort(lb) << 16) | __bfloat16_as_ushort(la);
    return ((uint32_t)__bfloat16_as_ushort(hb) << 16) | __bfloat16_as_ushort(ha);
}
__device__ __forceinline__ ushort2 split2(float x, float y, ushort2* lo) {
    __nv_bfloat16 hx = __float2bfloat16(x), hy = __float2bfloat16(y);
    lo->x = __bfloat16_as_ushort(__float2bfloat16(x - __bfloat162float(hx)));
    lo->y = __bfloat16_as_ushort(__float2bfloat16(y - __bfloat162float(hy)));
    ushort2 h; h.x = __bfloat16_as_ushort(hx); h.y = __bfloat16_as_ushort(hy);
    return h;
}

// ---------------------------------------------------------------------------
// RoPE cos/sin table (same numerics as the verified rope_split)
// ---------------------------------------------------------------------------
__global__ void init_tables(const int* __restrict__ tp, float2* __restrict__ cs_tab)
{
    int s = blockIdx.x, i = threadIdx.x;   // 2048 x 32
    float pos = (float)tp[s];
    double fr = exp(-((double)(2 * i) / (double)D_K) * log(10000.0));
    float ang = pos * (float)fr;
    float sn, csn;
    sincosf(ang, &sn, &csn);
    cs_tab[s * 32 + i] = make_float2(csn, sn);
}

// ---------------------------------------------------------------------------
// Per-row int8 2-limb quantization, one WARP per row (K = 1024).
// ---------------------------------------------------------------------------
__global__ __launch_bounds__(256) void quant_rows(
    const float* __restrict__ in, char4* __restrict__ h1, char4* __restrict__ h0,
    float* __restrict__ scale)
{
    const int warp = threadIdx.x >> 5, lane = threadIdx.x & 31;
    const int r = blockIdx.x * 8 + warp;
    const float4* row = (const float4*)(in + (size_t)r * 1024);

    float4 v[8];
#pragma unroll
    for (int j = 0; j < 8; j++) v[j] = row[lane + 32 * j];

    float m = 0.0f;
#pragma unroll
    for (int j = 0; j < 8; j++)
        m = fmaxf(m, fmaxf(fmaxf(fabsf(v[j].x), fabsf(v[j].y)),
                           fmaxf(fabsf(v[j].z), fabsf(v[j].w))));
#pragma unroll
    for (int off = 16; off >= 1; off >>= 1)
        m = fmaxf(m, __shfl_xor_sync(0xffffffffu, m, off));
    m = fmaxf(m, 1e-30f);
    const float inv = 16256.0f / m;

#pragma unroll
    for (int j = 0; j < 8; j++) {
        char4 c1, c0;
        int a1, a0;
        q2limb(v[j].x, inv, &a1, &a0); c1.x = (char)a1; c0.x = (char)a0;
        q2limb(v[j].y, inv, &a1, &a0); c1.y = (char)a1; c0.y = (char)a0;
        q2limb(v[j].z, inv, &a1, &a0); c1.z = (char)a1; c0.z = (char)a0;
        q2limb(v[j].w, inv, &a1, &a0); c1.w = (char)a1; c0.w = (char)a0;
        h1[(size_t)r * 256 + lane + 32 * j] = c1;
        h0[(size_t)r * 256 + lane + 32 * j] = c0;
    }
    if (lane == 0) scale[r] = m * (1.0f / 16256.0f);
}

// ---------------------------------------------------------------------------
// Int8 IMMA GEMM core (round-12 verified): BM=64 x BN=128, 3-stage ring.
// ---------------------------------------------------------------------------
#define IROWB 80
#define I_A1 0
#define I_A0 5120
#define I_B1 10240
#define I_B0 20480
#define ISTG 30720
#define NSTAGE 3
#define ISMEM (NSTAGE * ISTG + 1024)   // 93184
#define INKT 16

struct GemmCore {
    uint32_t sb;
    int tid, wid, lane, m0, n0, warp_m, warp_n;
    int a_row, a_byte, b_row, b_byte;
    const int8_t *A1, *A0, *B1, *B0;
    char* smem;

    __device__ __forceinline__ void load_stage(int kt, int s) {
        const int kbase = kt * 64;
        const uint32_t st = sb + s * ISTG;
        {
            int row = tid >> 2, c16 = tid & 3;
            uint32_t d = (uint32_t)(row * IROWB + c16 * 16);
            size_t ga = (size_t)(m0 + row) * 1024 + kbase + c16 * 16;
            cpasync16(st + I_A1 + d, A1 + ga);
            cpasync16(st + I_A0 + d, A0 + ga);
        }
#pragma unroll
        for (int i = tid; i < 512; i += 256) {
            int row = i >> 2, c16 = i & 3;
            uint32_t d = (uint32_t)(row * IROWB + c16 * 16);
            size_t gb = (size_t)(n0 + row) * 1024 + kbase + c16 * 16;
            cpasync16(st + I_B1 + d, B1 + gb);
            cpasync16(st + I_B0 + d, B0 + gb);
        }
    }

    __device__ __forceinline__ void run(int (*acc1)[4][4], int (*acc2)[4][4]) {
        load_stage(0, 0); CPASYNC_COMMIT();
        load_stage(1, 1); CPASYNC_COMMIT();

        for (int kt = 0; kt < INKT; kt++) {
            const int s = kt % NSTAGE;
            CPASYNC_WAIT1();
            __syncthreads();
            if (kt + 2 < INKT) load_stage(kt + 2, (kt + 2) % NSTAGE);
            CPASYNC_COMMIT();

            const uint32_t st = sb + s * ISTG;
#pragma unroll
            for (int ks = 0; ks < 2; ks++) {
                const int kb = ks * 32;
                uint32_t a1f[2][4], a0f[2][4], b1f[2][4], b0f[2][4];
#pragma unroll
                for (int mt = 0; mt < 2; mt++) {
                    uint32_t off = (uint32_t)((warp_m + mt * 16 + a_row) * IROWB + kb + a_byte);
                    ldm_x4(a1f[mt], st + I_A1 + off);
                    ldm_x4(a0f[mt], st + I_A0 + off);
                }
#pragma unroll
                for (int bt = 0; bt < 2; bt++) {
                    uint32_t off = (uint32_t)((warp_n + bt * 16 + b_row) * IROWB + kb + b_byte);
                    ldm_x4(b1f[bt], st + I_B1 + off);
                    ldm_x4(b0f[bt], st + I_B0 + off);
                }
#pragma unroll
                for (int mt = 0; mt < 2; mt++)
#pragma unroll
                    for (int nt = 0; nt < 4; nt++) {
                        uint32_t* B1p = &b1f[nt >> 1][(nt & 1) * 2];
                        uint32_t* B0p = &b0f[nt >> 1][(nt & 1) * 2];
                        mma_s8(acc1[mt][nt], a1f[mt], B1p);
                        mma_s8(acc2[mt][nt], a1f[mt], B0p);
                        mma_s8(acc2[mt][nt], a0f[mt], B1p);
                    }
            }
        }
    }
};

__device__ __forceinline__ void gemm_init(GemmCore& g, char* smem,
    const int8_t* A1, const int8_t* A0, const int8_t* B1, const int8_t* B0,
    int m0, int n0)
{
    g.smem = smem;
    g.sb = smem_u32(smem);
    g.tid = threadIdx.x; g.wid = g.tid >> 5; g.lane = g.tid & 31;
    g.m0 = m0; g.n0 = n0;
    g.warp_m = (g.wid >> 2) * 32; g.warp_n = (g.wid & 3) * 32;
    int l7 = g.lane & 7, gg = g.lane >> 3;
    g.a_row = (gg & 1) * 8 + l7; g.a_byte = (gg >> 1) * 16;
    g.b_row = (gg >> 1) * 8 + l7; g.b_byte = (gg & 1) * 16;
    g.A1 = A1; g.A0 = A0; g.B1 = B1; g.B0 = B0;
}

// Fused QKV kernel: blockIdx.z selects weight + output + epilogue mode.
__global__ __launch_bounds__(256, 2) void gemm_qkv(
    const int8_t* __restrict__ X1, const int8_t* __restrict__ X0,
    const int8_t* __restrict__ Wb1, const int8_t* __restrict__ Wb0,
    const float* __restrict__ sX, const float* __restrict__ sWb,
    __nv_bfloat16* __restrict__ qhi, __nv_bfloat16* __restrict__ qlo,
    __nv_bfloat16* __restrict__ khi, __nv_bfloat16* __restrict__ klo,
    __nv_bfloat16* __restrict__ vhi, __nv_bfloat16* __restrict__ vlo,
    const float2* __restrict__ cs_tab)
{
    extern __shared__ char smem[];
    const int z = blockIdx.z;
    const int m0 = blockIdx.y * 64, n0 = blockIdx.x * 128;
    const size_t WSZ = (size_t)D_MODEL * D_MODEL;

    GemmCore g;
    gemm_init(g, smem, X1, X0, Wb1 + z * WSZ, Wb0 + z * WSZ, m0, n0);

    float* sAs = (float*)(smem + NSTAGE * ISTG);
    float* sBs = sAs + 64;
    if (g.tid < 64) sAs[g.tid] = sX[m0 + g.tid];
    else if (g.tid < 192) sBs[g.tid - 64] = sWb[z * D_MODEL + n0 + g.tid - 64];

    int acc1[2][4][4], acc2[2][4][4];
#pragma unroll
    for (int i = 0; i < 2; i++)
#pragma unroll
        for (int j = 0; j < 4; j++)
#pragma unroll
            for (int k = 0; k < 4; k++) { acc1[i][j][k] = 0; acc2[i][j][k] = 0; }

    g.run(acc1, acc2);

    __nv_bfloat16* Ohi = (z == 0) ? qhi : (z == 1) ? khi : vhi;
    __nv_bfloat16* Olo = (z == 0) ? qlo : (z == 1) ? klo : vlo;
    const float qscale = (z == 0) ? 0.125f : 1.0f;
    const bool do_rope = (z < 2);
    const int lane = g.lane;

#pragma unroll
    for (int mt = 0; mt < 2; mt++) {
#pragma unroll
        for (int nt = 0; nt < 4; nt++) {
            int r = g.warp_m + mt * 16 + (lane >> 2);
            int c = g.warp_n + nt * 8 + (lane & 3) * 2;
            float fr0 = 128.0f * sAs[r],  fr1 = 128.0f * sAs[r + 8];
            float sc0 = sBs[c], sc1 = sBs[c + 1];
            float2 v0, v1;
            v0.x = fr0 * sc0 * fmaf(128.0f, (float)acc1[mt][nt][0], (float)acc2[mt][nt][0]);
            v0.y = fr0 * sc1 * fmaf(128.0f, (float)acc1[mt][nt][1], (float)acc2[mt][nt][1]);
            v1.x = fr1 * sc0 * fmaf(128.0f, (float)acc1[mt][nt][2], (float)acc2[mt][nt][2]);
            v1.y = fr1 * sc1 * fmaf(128.0f, (float)acc1[mt][nt][3], (float)acc2[mt][nt][3]);

            size_t o0 = (size_t)(m0 + r) * 1024 + n0 + c;
            size_t o1 = (size_t)(m0 + r + 8) * 1024 + n0 + c;

            if (do_rope) {
                int i = (c & 63) >> 1;
                int s0 = (m0 + r) & (SEQ - 1), s1 = (m0 + r + 8) & (SEQ - 1);
                float2 cs0 = __ldg(&cs_tab[s0 * 32 + i]);
                float2 cs1 = __ldg(&cs_tab[s1 * 32 + i]);
                float nx = cs0.x * v0.x - cs0.y * v0.y;
                float ny = cs0.x * v0.y + cs0.y * v0.x;
                v0.x = nx * qscale; v0.y = ny * qscale;
                nx = cs1.x * v1.x - cs1.y * v1.y;
                ny = cs1.x * v1.y + cs1.y * v1.x;
                v1.x = nx * qscale; v1.y = ny * qscale;
            }
            ushort2 lo;
            ushort2 hi = split2(v0.x, v0.y, &lo);
            *(ushort2*)&Ohi[o0] = hi;
            *(ushort2*)&Olo[o0] = lo;
            hi = split2(v1.x, v1.y, &lo);
            *(ushort2*)&Ohi[o1] = hi;
            *(ushort2*)&Olo[o1] = lo;
        }
    }
}

// Output projection: fp32 C.
__global__ __launch_bounds__(256, 2) void gemm_out(
    const int8_t* __restrict__ A1, const int8_t* __restrict__ A0,
    const int8_t* __restrict__ B1, const int8_t* __restrict__ B0,
    const float* __restrict__ sA, const float* __restrict__ sB,
    float* __restrict__ C)
{
    extern __shared__ char smem[];
    const int m0 = blockIdx.y * 64, n0 = blockIdx.x * 128;

    GemmCore g;
    gemm_init(g, smem, A1, A0, B1, B0, m0, n0);

    float* sAs = (float*)(smem + NSTAGE * ISTG);
    float* sBs = sAs + 64;
    if (g.tid < 64) sAs[g.tid] = sA[m0 + g.tid];
    else if (g.tid < 192) sBs[g.tid - 64] = sB[n0 + g.tid - 64];

    int acc1[2][4][4], acc2[2][4][4];
#pragma unroll
    for (int i = 0; i < 2; i++)
#pragma unroll
        for (int j = 0; j < 4; j++)
#pragma unroll
            for (int k = 0; k < 4; k++) { acc1[i][j][k] = 0; acc2[i][j][k] = 0; }

    g.run(acc1, acc2);

    const int lane = g.lane;
#pragma unroll
    for (int mt = 0; mt < 2; mt++) {
#pragma unroll
        for (int nt = 0; nt < 4; nt++) {
            int r = g.warp_m + mt * 16 + (lane >> 2);
            int c = g.warp_n + nt * 8 + (lane & 3) * 2;
            float fr0 = 128.0f * sAs[r],  fr1 = 128.0f * sAs[r + 8];
            float sc0 = sBs[c], sc1 = sBs[c + 1];
            float2 v0, v1;
            v0.x = fr0 * sc0 * fmaf(128.0f, (float)acc1[mt][nt][0], (float)acc2[mt][nt][0]);
            v0.y = fr0 * sc1 * fmaf(128.0f, (float)acc1[mt][nt][1], (float)acc2[mt][nt][1]);
            v1.x = fr1 * sc0 * fmaf(128.0f, (float)acc1[mt][nt][2], (float)acc2[mt][nt][2]);
            v1.y = fr1 * sc1 * fmaf(128.0f, (float)acc1[mt][nt][3], (float)acc2[mt][nt][3]);
            *(float2*)&C[(size_t)(m0 + r) * 1024 + n0 + c] = v0;
            *(float2*)&C[(size_t)(m0 + r + 8) * 1024 + n0 + c] = v1;
        }
    }
}

// ---------------------------------------------------------------------------
// Flash attention, bf16 hi/lo 3-term, BM=128 (256 thr, 8 warps x 16 rows).
// BN=64 keys/tile; K/V tiles now amortized over 2x q-rows.
// ---------------------------------------------------------------------------
#define AROWB 144
#define ASQ_HI 0
#define ASQ_LO 18432
#define AST_BASE 36864
#define AST_SIZE 36864
#define AK_HI 0
#define AK_LO 9216
#define AV_HI 18432
#define AV_LO 27648
#define ATTN_SMEM (AST_BASE + 2 * AST_SIZE)   // 110592

__global__ __launch_bounds__(256, 1) void attn_mma(
    const __nv_bfloat16* __restrict__ Qhi, const __nv_bfloat16* __restrict__ Qlo,
    const __nv_bfloat16* __restrict__ Khi, const __nv_bfloat16* __restrict__ Klo,
    const __nv_bfloat16* __restrict__ Vhi, const __nv_bfloat16* __restrict__ Vlo,
    float* __restrict__ O)
{
    extern __shared__ char smem[];
    const uint32_t sb = smem_u32(smem);
    const int tid = threadIdx.x, wid = tid >> 5, lane = tid & 31;
    const int qbi = gridDim.x - 1 - blockIdx.x;     // long diagonals first
    const int bh = blockIdx.y, b = bh >> 4, h = bh & 15;
    const size_t base = (size_t)b * SEQ * D_MODEL + (size_t)h * D_K;
    const int q0 = qbi * 128, wm = wid * 16;
    const int nkt = 2 * qbi + 2;

    const int l7 = lane & 7, g = lane >> 3;
    const int a_row = (g & 1) * 8 + l7, a_byte = (g >> 1) * 16;
    const int b_row = (g >> 1) * 8 + l7, b_byte = (g & 1) * 16;
    const int v_row = ((lane >> 3) & 1) * 8 + l7, v_byte = (lane >> 4) * 16;

    // Q tile: 128 rows hi/lo
    for (int i = tid; i < 1024; i += 256) {
        int r = i >> 3, c = i & 7;
        size_t gq = base + (size_t)(q0 + r) * D_MODEL + c * 8;
        uint32_t d = (uint32_t)(r * AROWB + c * 16);
        cpasync16(sb + ASQ_HI + d, Qhi + gq);
        cpasync16(sb + ASQ_LO + d, Qlo + gq);
    }
    auto load_kv = [&](int kb, int s) {
        uint32_t st = sb + AST_BASE + s * AST_SIZE;
        int k0 = kb * 64;
        for (int i = tid; i < 512; i += 256) {
            int r = i >> 3, c = i & 7;
            size_t gk = base + (size_t)(k0 + r) * D_MODEL + c * 8;
            uint32_t d = (uint32_t)(r * AROWB + c * 16);
            cpasync16(st + AK_HI + d, Khi + gk);
            cpasync16(st + AK_LO + d, Klo + gk);
            cpasync16(st + AV_HI + d, Vhi + gk);
            cpasync16(st + AV_LO + d, Vlo + gk);
        }
    };
    load_kv(0, 0); CPASYNC_COMMIT();
    load_kv(1, 1); CPASYNC_COMMIT();

    uint32_t qh[4][4], ql[4][4];
    float oacc[8][4];
#pragma unroll
    for (int dt = 0; dt < 8; dt++)
#pragma unroll
        for (int j = 0; j < 4; j++) oacc[dt][j] = 0.0f;
    float mi0 = -1e30f, mi1 = -1e30f, li0 = 0.0f, li1 = 0.0f;

    for (int kb = 0; kb < nkt; kb++) {
        CPASYNC_WAIT1();
        __syncthreads();

        if (kb == 0) {
#pragma unroll
            for (int ks = 0; ks < 4; ks++) {
                uint32_t off = (uint32_t)((wm + a_row) * AROWB + ks * 32 + a_byte);
                ldm_x4(qh[ks], sb + ASQ_HI + off);
                ldm_x4(ql[ks], sb + ASQ_LO + off);
            }
        }

        const uint32_t st = sb + AST_BASE + (kb & 1) * AST_SIZE;

        float s[8][4];
#pragma unroll
        for (int nt = 0; nt < 8; nt++)
#pragma unroll
            for (int j = 0; j < 4; j++) s[nt][j] = 0.0f;

#pragma unroll
        for (int ks = 0; ks < 4; ks++) {
            uint32_t kh[4][4], kl[4][4];
#pragma unroll
            for (int bt = 0; bt < 4; bt++) {
                uint32_t off = (uint32_t)((bt * 16 + b_row) * AROWB + ks * 32 + b_byte);
                ldm_x4(kh[bt], st + AK_HI + off);
                ldm_x4(kl[bt], st + AK_LO + off);
            }
#pragma unroll
            for (int nt = 0; nt < 8; nt++) {
                uint32_t* BH = &kh[nt >> 1][(nt & 1) * 2];
                uint32_t* BL = &kl[nt >> 1][(nt & 1) * 2];
                mma_bf16(s[nt], qh[ks], BH);
                mma_bf16(s[nt], qh[ks], BL);
                mma_bf16(s[nt], ql[ks], BH);
            }
        }

        // causal mask on the last two k-tiles (global row/col compare)
        if (kb >= 2 * qbi) {
            const int grow0 = q0 + wm + (lane >> 2), grow1 = grow0 + 8;
            const int gc = kb * 64 + (lane & 3) * 2;
#pragma unroll
            for (int nt = 0; nt < 8; nt++) {
                int c0 = gc + nt * 8;
                if (c0 > grow0)     s[nt][0] = -1e30f;
                if (c0 + 1 > grow0) s[nt][1] = -1e30f;
                if (c0 > grow1)     s[nt][2] = -1e30f;
                if (c0 + 1 > grow1) s[nt][3] = -1e30f;
            }
        }

        float rm0 = -1e30f, rm1 = -1e30f;
#pragma unroll
        for (int nt = 0; nt < 8; nt++) {
            rm0 = fmaxf(rm0, fmaxf(s[nt][0], s[nt][1]));
            rm1 = fmaxf(rm1, fmaxf(s[nt][2], s[nt][3]));
        }
        rm0 = fmaxf(rm0, __shfl_xor_sync(0xffffffffu, rm0, 1));
        rm0 = fmaxf(rm0, __shfl_xor_sync(0xffffffffu, rm0, 2));
        rm1 = fmaxf(rm1, __shfl_xor_sync(0xffffffffu, rm1, 1));
        rm1 = fmaxf(rm1, __shfl_xor_sync(0xffffffffu, rm1, 2));
        float mn0 = fmaxf(mi0, rm0), mn1 = fmaxf(mi1, rm1);
        float al0 = __expf(mi0 - mn0), al1 = __expf(mi1 - mn1);
        float rs0 = 0.0f, rs1 = 0.0f;
#pragma unroll
        for (int nt = 0; nt < 8; nt++) {
            s[nt][0] = __expf(s[nt][0] - mn0);
            s[nt][1] = __expf(s[nt][1] - mn0);
            s[nt][2] = __expf(s[nt][2] - mn1);
            s[nt][3] = __expf(s[nt][3] - mn1);
            rs0 += s[nt][0] + s[nt][1];
            rs1 += s[nt][2] + s[nt][3];
        }
        rs0 += __shfl_xor_sync(0xffffffffu, rs0, 1);
        rs0 += __shfl_xor_sync(0xffffffffu, rs0, 2);
        rs1 += __shfl_xor_sync(0xffffffffu, rs1, 1);
        rs1 += __shfl_xor_sync(0xffffffffu, rs1, 2);
        li0 = li0 * al0 + rs0; li1 = li1 * al1 + rs1;
        mi0 = mn0; mi1 = mn1;
#pragma unroll
        for (int dt = 0; dt < 8; dt++) {
            oacc[dt][0] *= al0; oacc[dt][1] *= al0;
            oacc[dt][2] *= al1; oacc[dt][3] *= al1;
        }

#pragma unroll
        for (int ks = 0; ks < 4; ks++) {
            uint32_t ph[4], pl[4];
            ph[0] = pack_split(s[2 * ks][0],     s[2 * ks][1],     &pl[0]);
            ph[1] = pack_split(s[2 * ks][2],     s[2 * ks][3],     &pl[1]);
            ph[2] = pack_split(s[2 * ks + 1][0], s[2 * ks + 1][1], &pl[2]);
            ph[3] = pack_split(s[2 * ks + 1][2], s[2 * ks + 1][3], &pl[3]);
            uint32_t vh[4][4], vl[4][4];
#pragma unroll
            for (int dp = 0; dp < 4; dp++) {
                uint32_t off = (uint32_t)((ks * 16 + v_row) * AROWB + dp * 32 + v_byte);
                ldm_x4_t(vh[dp], st + AV_HI + off);
                ldm_x4_t(vl[dp], st + AV_LO + off);
            }
#pragma unroll
            for (int dt = 0; dt < 8; dt++) {
                uint32_t* BH = &vh[dt >> 1][(dt & 1) * 2];
                uint32_t* BL = &vl[dt >> 1][(dt & 1) * 2];
                mma_bf16(oacc[dt], ph, BH);
                mma_bf16(oacc[dt], ph, BL);
                mma_bf16(oacc[dt], pl, BH);
            }
        }

        __syncthreads();
        if (kb + 2 < nkt) load_kv(kb + 2, kb & 1);
        CPASYNC_COMMIT();
    }

    float i0 = 1.0f / li0, i1 = 1.0f / li1;
    int r0 = q0 + wm + (lane >> 2);
    int cb = (lane & 3) * 2;
#pragma unroll
    for (int dt = 0; dt < 8; dt++) {
        float2 v0 = make_float2(oacc[dt][0] * i0, oacc[dt][1] * i0);
        float2 v1 = make_float2(oacc[dt][2] * i1, oacc[dt][3] * i1);
        *(float2*)&O[base + (size_t)r0 * D_MODEL + dt * 8 + cb] = v0;
        *(float2*)&O[base + (size_t)(r0 + 8) * D_MODEL + dt * 8 + cb] = v1;
    }
}

// ---------------------------------------------------------------------------
// Launch
// ---------------------------------------------------------------------------
extern "C" void kernel_launch(void* const* d_in, const int* in_sizes, int n_in,
                              void* d_out, int out_size)
{
    const float* x  = (const float*)d_in[0];
    const int*   tp = (const int*)d_in[1];
    const float* W[4] = { (const float*)d_in[2], (const float*)d_in[3],
                          (const float*)d_in[4], (const float*)d_in[5] };
    float* out = (float*)d_out;

    float *gA, *sx, *sa, *sw;
    int8_t *x1, *x0, *a1, *a0, *w1, *w0;
    __nv_bfloat16 *qhi, *qlo, *khi, *klo, *vhi, *vlo;
    float2* cs;
    cudaGetSymbolAddress((void**)&gA, g_A);
    cudaGetSymbolAddress((void**)&x1, g_x1);
    cudaGetSymbolAddress((void**)&x0, g_x0);
    cudaGetSymbolAddress((void**)&a1, g_a1);
    cudaGetSymbolAddress((void**)&a0, g_a0);
    cudaGetSymbolAddress((void**)&w1, g_w1);
    cudaGetSymbolAddress((void**)&w0, g_w0);
    cudaGetSymbolAddress((void**)&sx, g_sx);
    cudaGetSymbolAddress((void**)&sa, g_sa);
    cudaGetSymbolAddress((void**)&sw, g_sw);
    cudaGetSymbolAddress((void**)&qhi, g_qhi);
    cudaGetSymbolAddress((void**)&qlo, g_qlo);
    cudaGetSymbolAddress((void**)&khi, g_khi);
    cudaGetSymbolAddress((void**)&klo, g_klo);
    cudaGetSymbolAddress((void**)&vhi, g_vhi);
    cudaGetSymbolAddress((void**)&vlo, g_vlo);
    cudaGetSymbolAddress((void**)&cs, g_cs);

    const int WSZ = D_MODEL * D_MODEL;

    init_tables<<<SEQ, 32>>>(tp, cs);
    quant_rows<<<M_TOTAL / 8, 256>>>(x, (char4*)x1, (char4*)x0, sx);
    for (int i = 0; i < 4; i++)
        quant_rows<<<D_MODEL / 8, 256>>>(W[i], (char4*)(w1 + (size_t)i * WSZ),
                                         (char4*)(w0 + (size_t)i * WSZ), sw + i * D_MODEL);

    cudaFuncSetAttribute(gemm_qkv, cudaFuncAttributeMaxDynamicSharedMemorySize, ISMEM);
    cudaFuncSetAttribute(gemm_out, cudaFuncAttributeMaxDynamicSharedMemorySize, ISMEM);

    gemm_qkv<<<dim3(D_MODEL / 128, M_TOTAL / 64, 3), 256, ISMEM>>>(
        x1, x0, w1, w0, sx, sw, qhi, qlo, khi, klo, vhi, vlo, cs);

    cudaFuncSetAttribute(attn_mma, cudaFuncAttributeMaxDynamicSharedMemorySize, ATTN_SMEM);
    attn_mma<<<dim3(SEQ / 128, BATCH * NUM_HEADS), 256, ATTN_SMEM>>>(
        qhi, qlo, khi, klo, vhi, vlo, gA);

    quant_rows<<<M_TOTAL / 8, 256>>>(gA, (char4*)a1, (char4*)a0, sa);
    gemm_out<<<dim3(D_MODEL / 128, M_TOTAL / 64), 256, ISMEM>>>(
        a1, a0, w1 + 3 * (size_t)WSZ, w0 + 3 * (size_t)WSZ, sa, sw + 3 * D_MODEL, out);
}

// round 17
// speedup vs baseline: 1.0336x; 1.0336x over previous
#include <cuda_runtime.h>
#include <cuda_bf16.h>
#include <math.h>
#include <stdint.h>

// Problem constants
#define D_MODEL 1024
#define NUM_HEADS 16
#define D_K 64
#define BATCH 4
#define SEQ 2048
#define M_TOTAL (BATCH * SEQ)   // 8192

// ---------------------------------------------------------------------------
// Scratch (device globals)
// ---------------------------------------------------------------------------
__device__ float g_A[M_TOTAL * D_MODEL];
__device__ int8_t g_x1[M_TOTAL * D_MODEL];
__device__ int8_t g_x0[M_TOTAL * D_MODEL];
__device__ int8_t g_a1[M_TOTAL * D_MODEL];
__device__ int8_t g_a0[M_TOTAL * D_MODEL];
__device__ int8_t g_w1[4][D_MODEL * D_MODEL];
__device__ int8_t g_w0[4][D_MODEL * D_MODEL];
__device__ float  g_sx[M_TOTAL];
__device__ float  g_sa[M_TOTAL];
__device__ float  g_sw[4][D_MODEL];
__device__ __nv_bfloat16 g_qhi[M_TOTAL * D_MODEL];
__device__ __nv_bfloat16 g_qlo[M_TOTAL * D_MODEL];
__device__ __nv_bfloat16 g_khi[M_TOTAL * D_MODEL];
__device__ __nv_bfloat16 g_klo[M_TOTAL * D_MODEL];
__device__ __nv_bfloat16 g_vhi[M_TOTAL * D_MODEL];
__device__ __nv_bfloat16 g_vlo[M_TOTAL * D_MODEL];
__device__ float2 g_cs[SEQ * 32];      // (cos, sin) per (position, pair)

// ---------------------------------------------------------------------------
// PTX helpers
// ---------------------------------------------------------------------------
__device__ __forceinline__ uint32_t smem_u32(const void* p) {
    uint32_t a;
    asm("{ .reg .u64 t; cvta.to.shared.u64 t, %1; cvt.u32.u64 %0, t; }" : "=r"(a) : "l"(p));
    return a;
}
__device__ __forceinline__ void cpasync16(uint32_t dst, const void* src) {
    asm volatile("cp.async.ca.shared.global [%0], [%1], 16;" :: "r"(dst), "l"(src));
}
#define CPASYNC_COMMIT() asm volatile("cp.async.commit_group;" ::: "memory")
#define CPASYNC_WAIT1()  asm volatile("cp.async.wait_group 1;" ::: "memory")

__device__ __forceinline__ void ldm_x4(uint32_t* r, uint32_t addr) {
    asm volatile("ldmatrix.sync.aligned.m8n8.x4.shared.b16 {%0,%1,%2,%3}, [%4];"
        : "=r"(r[0]), "=r"(r[1]), "=r"(r[2]), "=r"(r[3]) : "r"(addr));
}
__device__ __forceinline__ void ldm_x4_t(uint32_t* r, uint32_t addr) {
    asm volatile("ldmatrix.sync.aligned.m8n8.x4.trans.shared.b16 {%0,%1,%2,%3}, [%4];"
        : "=r"(r[0]), "=r"(r[1]), "=r"(r[2]), "=r"(r[3]) : "r"(addr));
}
__device__ __forceinline__ void mma_bf16(float* c, const uint32_t* a, const uint32_t* b) {
    asm volatile("mma.sync.aligned.m16n8k16.row.col.f32.bf16.bf16.f32 "
        "{%0,%1,%2,%3}, {%4,%5,%6,%7}, {%8,%9}, {%0,%1,%2,%3};"
        : "+f"(c[0]), "+f"(c[1]), "+f"(c[2]), "+f"(c[3])
        : "r"(a[0]), "r"(a[1]), "r"(a[2]), "r"(a[3]), "r"(b[0]), "r"(b[1]));
}
__device__ __forceinline__ void mma_s8(int* c, const uint32_t* a, const uint32_t* b) {
    asm volatile("mma.sync.aligned.m16n8k32.row.col.s32.s8.s8.s32 "
        "{%0,%1,%2,%3}, {%4,%5,%6,%7}, {%8,%9}, {%0,%1,%2,%3};"
        : "+r"(c[0]), "+r"(c[1]), "+r"(c[2]), "+r"(c[3])
        : "r"(a[0]), "r"(a[1]), "r"(a[2]), "r"(a[3]), "r"(b[0]), "r"(b[1]));
}
__device__ __forceinline__ void q2limb(float v, float inv, int* l1, int* l0) {
    float t = fminf(fmaxf(rintf(v * inv), -16256.f), 16256.f);
    int a1 = __float2int_rn(t * (1.0f / 128.0f));
    *l1 = a1; *l0 = (int)t - (a1 << 7);
}
__device__ __forceinline__ uint32_t pack_split(float a, float b, uint32_t* lo) {
    __nv_bfloat16 ha = __float2bfloat16(a), hb = __float2bfloat16(b);
    __nv_bfloat16 la = __float2bfloat16(a - __bfloat162float(ha));
    __nv_bfloat16 lb = __float2bfloat16(b - __bfloat162float(hb));
    *lo = ((uint32_t)__bfloat16_as_ushort(lb) << 16) | __bfloat16_as_ushort(la);
    return ((uint32_t)__bfloat16_as_ushort(hb) << 16) | __bfloat16_as_ushort(ha);
}
__device__ __forceinline__ ushort2 split2(float x, float y, ushort2* lo) {
    __nv_bfloat16 hx = __float2bfloat16(x), hy = __float2bfloat16(y);
    lo->x = __bfloat16_as_ushort(__float2bfloat16(x - __bfloat162float(hx)));
    lo->y = __bfloat16_as_ushort(__float2bfloat16(y - __bfloat162float(hy)));
    ushort2 h; h.x = __bfloat16_as_ushort(hx); h.y = __bfloat16_as_ushort(hy);
    return h;
}

// ---------------------------------------------------------------------------
// Warp-per-row int8 2-limb quantization helper (K = 1024), round-13 verified.
// ---------------------------------------------------------------------------
__device__ __forceinline__ void quant_row_warp(
    const float* __restrict__ rowp, char4* __restrict__ h1, char4* __restrict__ h0,
    float* __restrict__ scale_out)
{
    const int lane = threadIdx.x & 31;
    const float4* row = (const float4*)rowp;

    float4 v[8];
#pragma unroll
    for (int j = 0; j < 8; j++) v[j] = row[lane + 32 * j];

    float m = 0.0f;
#pragma unroll
    for (int j = 0; j < 8; j++)
        m = fmaxf(m, fmaxf(fmaxf(fabsf(v[j].x), fabsf(v[j].y)),
                           fmaxf(fabsf(v[j].z), fabsf(v[j].w))));
#pragma unroll
    for (int off = 16; off >= 1; off >>= 1)
        m = fmaxf(m, __shfl_xor_sync(0xffffffffu, m, off));
    m = fmaxf(m, 1e-30f);
    const float inv = 16256.0f / m;

#pragma unroll
    for (int j = 0; j < 8; j++) {
        char4 c1, c0;
        int a1, a0;
        q2limb(v[j].x, inv, &a1, &a0); c1.x = (char)a1; c0.x = (char)a0;
        q2limb(v[j].y, inv, &a1, &a0); c1.y = (char)a1; c0.y = (char)a0;
        q2limb(v[j].z, inv, &a1, &a0); c1.z = (char)a1; c0.z = (char)a0;
        q2limb(v[j].w, inv, &a1, &a0); c1.w = (char)a1; c0.w = (char)a0;
        h1[lane + 32 * j] = c1;
        h0[lane + 32 * j] = c0;
    }
    if (lane == 0) *scale_out = m * (1.0f / 16256.0f);
}

// Standalone quant (post-attention A path)
__global__ __launch_bounds__(256) void quant_rows(
    const float* __restrict__ in, char4* __restrict__ h1, char4* __restrict__ h0,
    float* __restrict__ scale)
{
    const int r = blockIdx.x * 8 + (threadIdx.x >> 5);
    quant_row_warp(in + (size_t)r * 1024, h1 + (size_t)r * 256, h0 + (size_t)r * 256,
                   scale + r);
}

// ---------------------------------------------------------------------------
// Fused prologue: x quant (blocks 0..1023), weight quant (1024..1535),
// RoPE cs table (1536..1543). All independent -> one wave, one launch.
// ---------------------------------------------------------------------------
__global__ __launch_bounds__(256) void prologue(
    const float* __restrict__ x,
    const float* __restrict__ W0, const float* __restrict__ W1f,
    const float* __restrict__ W2, const float* __restrict__ W3,
    const int* __restrict__ tp,
    char4* __restrict__ x1, char4* __restrict__ x0, float* __restrict__ sx,
    char4* __restrict__ w1, char4* __restrict__ w0, float* __restrict__ sw,
    float2* __restrict__ cs_tab)
{
    const int blk = blockIdx.x, tid = threadIdx.x;
    if (blk < 1024) {
        const int r = blk * 8 + (tid >> 5);
        quant_row_warp(x + (size_t)r * 1024, x1 + (size_t)r * 256,
                       x0 + (size_t)r * 256, sx + r);
    } else if (blk < 1536) {
        const int rg = (blk - 1024) * 8 + (tid >> 5);   // 0..4095
        const int wi = rg >> 10, r = rg & 1023;
        const float* W = (wi == 0) ? W0 : (wi == 1) ? W1f : (wi == 2) ? W2 : W3;
        const size_t base = (size_t)wi * 262144 + (size_t)r * 256;   // char4 units
        quant_row_warp(W + (size_t)r * 1024, w1 + base, w0 + base,
                       sw + wi * 1024 + r);
    } else {
        const int s = (blk - 1536) * 256 + tid;         // 0..2047
        const float pos = (float)tp[s];
        for (int i = 0; i < 32; i++) {
            double fr = exp(-((double)(2 * i) / (double)D_K) * log(10000.0));
            float ang = pos * (float)fr;
            float sn, csn;
            sincosf(ang, &sn, &csn);
            cs_tab[s * 32 + i] = make_float2(csn, sn);
        }
    }
}

// ---------------------------------------------------------------------------
// Int8 IMMA GEMM core (round-12 verified): BM=64 x BN=128, 3-stage ring.
// ---------------------------------------------------------------------------
#define IROWB 80
#define I_A1 0
#define I_A0 5120
#define I_B1 10240
#define I_B0 20480
#define ISTG 30720
#define NSTAGE 3
#define ISMEM (NSTAGE * ISTG + 1024)   // 93184
#define INKT 16

struct GemmCore {
    uint32_t sb;
    int tid, wid, lane, m0, n0, warp_m, warp_n;
    int a_row, a_byte, b_row, b_byte;
    const int8_t *A1, *A0, *B1, *B0;
    char* smem;

    __device__ __forceinline__ void load_stage(int kt, int s) {
        const int kbase = kt * 64;
        const uint32_t st = sb + s * ISTG;
        {
            int row = tid >> 2, c16 = tid & 3;
            uint32_t d = (uint32_t)(row * IROWB + c16 * 16);
            size_t ga = (size_t)(m0 + row) * 1024 + kbase + c16 * 16;
            cpasync16(st + I_A1 + d, A1 + ga);
            cpasync16(st + I_A0 + d, A0 + ga);
        }
#pragma unroll
        for (int i = tid; i < 512; i += 256) {
            int row = i >> 2, c16 = i & 3;
            uint32_t d = (uint32_t)(row * IROWB + c16 * 16);
            size_t gb = (size_t)(n0 + row) * 1024 + kbase + c16 * 16;
            cpasync16(st + I_B1 + d, B1 + gb);
            cpasync16(st + I_B0 + d, B0 + gb);
        }
    }

    __device__ __forceinline__ void run(int (*acc1)[4][4], int (*acc2)[4][4]) {
        load_stage(0, 0); CPASYNC_COMMIT();
        load_stage(1, 1); CPASYNC_COMMIT();

        for (int kt = 0; kt < INKT; kt++) {
            const int s = kt % NSTAGE;
            CPASYNC_WAIT1();
            __syncthreads();
            if (kt + 2 < INKT) load_stage(kt + 2, (kt + 2) % NSTAGE);
            CPASYNC_COMMIT();

            const uint32_t st = sb + s * ISTG;
#pragma unroll
            for (int ks = 0; ks < 2; ks++) {
                const int kb = ks * 32;
                uint32_t a1f[2][4], a0f[2][4], b1f[2][4], b0f[2][4];
#pragma unroll
                for (int mt = 0; mt < 2; mt++) {
                    uint32_t off = (uint32_t)((warp_m + mt * 16 + a_row) * IROWB + kb + a_byte);
                    ldm_x4(a1f[mt], st + I_A1 + off);
                    ldm_x4(a0f[mt], st + I_A0 + off);
                }
#pragma unroll
                for (int bt = 0; bt < 2; bt++) {
                    uint32_t off = (uint32_t)((warp_n + bt * 16 + b_row) * IROWB + kb + b_byte);
                    ldm_x4(b1f[bt], st + I_B1 + off);
                    ldm_x4(b0f[bt], st + I_B0 + off);
                }
#pragma unroll
                for (int mt = 0; mt < 2; mt++)
#pragma unroll
                    for (int nt = 0; nt < 4; nt++) {
                        uint32_t* B1p = &b1f[nt >> 1][(nt & 1) * 2];
                        uint32_t* B0p = &b0f[nt >> 1][(nt & 1) * 2];
                        mma_s8(acc1[mt][nt], a1f[mt], B1p);
                        mma_s8(acc2[mt][nt], a1f[mt], B0p);
                        mma_s8(acc2[mt][nt], a0f[mt], B1p);
                    }
            }
        }
    }
};

__device__ __forceinline__ void gemm_init(GemmCore& g, char* smem,
    const int8_t* A1, const int8_t* A0, const int8_t* B1, const int8_t* B0,
    int m0, int n0)
{
    g.smem = smem;
    g.sb = smem_u32(smem);
    g.tid = threadIdx.x; g.wid = g.tid >> 5; g.lane = g.tid & 31;
    g.m0 = m0; g.n0 = n0;
    g.warp_m = (g.wid >> 2) * 32; g.warp_n = (g.wid & 3) * 32;
    int l7 = g.lane & 7, gg = g.lane >> 3;
    g.a_row = (gg & 1) * 8 + l7; g.a_byte = (gg >> 1) * 16;
    g.b_row = (gg >> 1) * 8 + l7; g.b_byte = (gg & 1) * 16;
    g.A1 = A1; g.A0 = A0; g.B1 = B1; g.B0 = B0;
}

// Fused QKV kernel: blockIdx.z selects weight + output + epilogue mode.
__global__ __launch_bounds__(256, 2) void gemm_qkv(
    const int8_t* __restrict__ X1, const int8_t* __restrict__ X0,
    const int8_t* __restrict__ Wb1, const int8_t* __restrict__ Wb0,
    const float* __restrict__ sX, const float* __restrict__ sWb,
    __nv_bfloat16* __restrict__ qhi, __nv_bfloat16* __restrict__ qlo,
    __nv_bfloat16* __restrict__ khi, __nv_bfloat16* __restrict__ klo,
    __nv_bfloat16* __restrict__ vhi, __nv_bfloat16* __restrict__ vlo,
    const float2* __restrict__ cs_tab)
{
    extern __shared__ char smem[];
    const int z = blockIdx.z;
    const int m0 = blockIdx.y * 64, n0 = blockIdx.x * 128;
    const size_t WSZ = (size_t)D_MODEL * D_MODEL;

    GemmCore g;
    gemm_init(g, smem, X1, X0, Wb1 + z * WSZ, Wb0 + z * WSZ, m0, n0);

    float* sAs = (float*)(smem + NSTAGE * ISTG);
    float* sBs = sAs + 64;
    if (g.tid < 64) sAs[g.tid] = sX[m0 + g.tid];
    else if (g.tid < 192) sBs[g.tid - 64] = sWb[z * D_MODEL + n0 + g.tid - 64];

    int acc1[2][4][4], acc2[2][4][4];
#pragma unroll
    for (int i = 0; i < 2; i++)
#pragma unroll
        for (int j = 0; j < 4; j++)
#pragma unroll
            for (int k = 0; k < 4; k++) { acc1[i][j][k] = 0; acc2[i][j][k] = 0; }

    g.run(acc1, acc2);

    __nv_bfloat16* Ohi = (z == 0) ? qhi : (z == 1) ? khi : vhi;
    __nv_bfloat16* Olo = (z == 0) ? qlo : (z == 1) ? klo : vlo;
    const float qscale = (z == 0) ? 0.125f : 1.0f;
    const bool do_rope = (z < 2);
    const int lane = g.lane;

#pragma unroll
    for (int mt = 0; mt < 2; mt++) {
#pragma unroll
        for (int nt = 0; nt < 4; nt++) {
            int r = g.warp_m + mt * 16 + (lane >> 2);
            int c = g.warp_n + nt * 8 + (lane & 3) * 2;
            float fr0 = 128.0f * sAs[r],  fr1 = 128.0f * sAs[r + 8];
            float sc0 = sBs[c], sc1 = sBs[c + 1];
            float2 v0, v1;
            v0.x = fr0 * sc0 * fmaf(128.0f, (float)acc1[mt][nt][0], (float)acc2[mt][nt][0]);
            v0.y = fr0 * sc1 * fmaf(128.0f, (float)acc1[mt][nt][1], (float)acc2[mt][nt][1]);
            v1.x = fr1 * sc0 * fmaf(128.0f, (float)acc1[mt][nt][2], (float)acc2[mt][nt][2]);
            v1.y = fr1 * sc1 * fmaf(128.0f, (float)acc1[mt][nt][3], (float)acc2[mt][nt][3]);

            size_t o0 = (size_t)(m0 + r) * 1024 + n0 + c;
            size_t o1 = (size_t)(m0 + r + 8) * 1024 + n0 + c;

            if (do_rope) {
                int i = (c & 63) >> 1;
                int s0 = (m0 + r) & (SEQ - 1), s1 = (m0 + r + 8) & (SEQ - 1);
                float2 cs0 = __ldg(&cs_tab[s0 * 32 + i]);
                float2 cs1 = __ldg(&cs_tab[s1 * 32 + i]);
                float nx = cs0.x * v0.x - cs0.y * v0.y;
                float ny = cs0.x * v0.y + cs0.y * v0.x;
                v0.x = nx * qscale; v0.y = ny * qscale;
                nx = cs1.x * v1.x - cs1.y * v1.y;
                ny = cs1.x * v1.y + cs1.y * v1.x;
                v1.x = nx * qscale; v1.y = ny * qscale;
            }
            ushort2 lo;
            ushort2 hi = split2(v0.x, v0.y, &lo);
            *(ushort2*)&Ohi[o0] = hi;
            *(ushort2*)&Olo[o0] = lo;
            hi = split2(v1.x, v1.y, &lo);
            *(ushort2*)&Ohi[o1] = hi;
            *(ushort2*)&Olo[o1] = lo;
        }
    }
}

// Output projection: fp32 C.
__global__ __launch_bounds__(256, 2) void gemm_out(
    const int8_t* __restrict__ A1, const int8_t* __restrict__ A0,
    const int8_t* __restrict__ B1, const int8_t* __restrict__ B0,
    const float* __restrict__ sA, const float* __restrict__ sB,
    float* __restrict__ C)
{
    extern __shared__ char smem[];
    const int m0 = blockIdx.y * 64, n0 = blockIdx.x * 128;

    GemmCore g;
    gemm_init(g, smem, A1, A0, B1, B0, m0, n0);

    float* sAs = (float*)(smem + NSTAGE * ISTG);
    float* sBs = sAs + 64;
    if (g.tid < 64) sAs[g.tid] = sA[m0 + g.tid];
    else if (g.tid < 192) sBs[g.tid - 64] = sB[n0 + g.tid - 64];

    int acc1[2][4][4], acc2[2][4][4];
#pragma unroll
    for (int i = 0; i < 2; i++)
#pragma unroll
        for (int j = 0; j < 4; j++)
#pragma unroll
            for (int k = 0; k < 4; k++) { acc1[i][j][k] = 0; acc2[i][j][k] = 0; }

    g.run(acc1, acc2);

    const int lane = g.lane;
#pragma unroll
    for (int mt = 0; mt < 2; mt++) {
#pragma unroll
        for (int nt = 0; nt < 4; nt++) {
            int r = g.warp_m + mt * 16 + (lane >> 2);
            int c = g.warp_n + nt * 8 + (lane & 3) * 2;
            float fr0 = 128.0f * sAs[r],  fr1 = 128.0f * sAs[r + 8];
            float sc0 = sBs[c], sc1 = sBs[c + 1];
            float2 v0, v1;
            v0.x = fr0 * sc0 * fmaf(128.0f, (float)acc1[mt][nt][0], (float)acc2[mt][nt][0]);
            v0.y = fr0 * sc1 * fmaf(128.0f, (float)acc1[mt][nt][1], (float)acc2[mt][nt][1]);
            v1.x = fr1 * sc0 * fmaf(128.0f, (float)acc1[mt][nt][2], (float)acc2[mt][nt][2]);
            v1.y = fr1 * sc1 * fmaf(128.0f, (float)acc1[mt][nt][3], (float)acc2[mt][nt][3]);
            *(float2*)&C[(size_t)(m0 + r) * 1024 + n0 + c] = v0;
            *(float2*)&C[(size_t)(m0 + r + 8) * 1024 + n0 + c] = v1;
        }
    }
}

// ---------------------------------------------------------------------------
// Flash attention via mma.sync, bf16 hi/lo 3-term (round-13 verified, BM=64).
// ---------------------------------------------------------------------------
#define AROWB 144
#define ASQ_HI 0
#define ASQ_LO 9216
#define AST_BASE 18432
#define AST_SIZE 36864
#define AK_HI 0
#define AK_LO 9216
#define AV_HI 18432
#define AV_LO 27648
#define ATTN_SMEM (AST_BASE + 2 * AST_SIZE)   // 92160

__global__ __launch_bounds__(128, 2) void attn_mma(
    const __nv_bfloat16* __restrict__ Qhi, const __nv_bfloat16* __restrict__ Qlo,
    const __nv_bfloat16* __restrict__ Khi, const __nv_bfloat16* __restrict__ Klo,
    const __nv_bfloat16* __restrict__ Vhi, const __nv_bfloat16* __restrict__ Vlo,
    float* __restrict__ O)
{
    extern __shared__ char smem[];
    const uint32_t sb = smem_u32(smem);
    const int tid = threadIdx.x, wid = tid >> 5, lane = tid & 31;
    const int qb = gridDim.x - 1 - blockIdx.x;
    const int bh = blockIdx.y, b = bh >> 4, h = bh & 15;
    const size_t base = (size_t)b * SEQ * D_MODEL + (size_t)h * D_K;
    const int q0 = qb * 64, wm = wid * 16;

    const int l7 = lane & 7, g = lane >> 3;
    const int a_row = (g & 1) * 8 + l7, a_byte = (g >> 1) * 16;
    const int b_row = (g >> 1) * 8 + l7, b_byte = (g & 1) * 16;
    const int v_row = ((lane >> 3) & 1) * 8 + l7, v_byte = (lane >> 4) * 16;

    for (int i = tid; i < 512; i += 128) {
        int r = i >> 3, c = i & 7;
        size_t gq = base + (size_t)(q0 + r) * D_MODEL + c * 8;
        uint32_t d = (uint32_t)(r * AROWB + c * 16);
        cpasync16(sb + ASQ_HI + d, Qhi + gq);
        cpasync16(sb + ASQ_LO + d, Qlo + gq);
    }
    auto load_kv = [&](int kb, int s) {
        uint32_t st = sb + AST_BASE + s * AST_SIZE;
        int k0 = kb * 64;
        for (int i = tid; i < 512; i += 128) {
            int r = i >> 3, c = i & 7;
            size_t gk = base + (size_t)(k0 + r) * D_MODEL + c * 8;
            uint32_t d = (uint32_t)(r * AROWB + c * 16);
            cpasync16(st + AK_HI + d, Khi + gk);
            cpasync16(st + AK_LO + d, Klo + gk);
            cpasync16(st + AV_HI + d, Vhi + gk);
            cpasync16(st + AV_LO + d, Vlo + gk);
        }
    };
    load_kv(0, 0); CPASYNC_COMMIT();
    if (qb >= 1) load_kv(1, 1);
    CPASYNC_COMMIT();

    uint32_t qh[4][4], ql[4][4];
    float oacc[8][4];
#pragma unroll
    for (int dt = 0; dt < 8; dt++)
#pragma unroll
        for (int j = 0; j < 4; j++) oacc[dt][j] = 0.0f;
    float mi0 = -1e30f, mi1 = -1e30f, li0 = 0.0f, li1 = 0.0f;

    for (int kb = 0; kb <= qb; kb++) {
        CPASYNC_WAIT1();
        __syncthreads();

        if (kb == 0) {
#pragma unroll
            for (int ks = 0; ks < 4; ks++) {
                uint32_t off = (uint32_t)((wm + a_row) * AROWB + ks * 32 + a_byte);
                ldm_x4(qh[ks], sb + ASQ_HI + off);
                ldm_x4(ql[ks], sb + ASQ_LO + off);
            }
        }

        const uint32_t st = sb + AST_BASE + (kb & 1) * AST_SIZE;

        float s[8][4];
#pragma unroll
        for (int nt = 0; nt < 8; nt++)
#pragma unroll
            for (int j = 0; j < 4; j++) s[nt][j] = 0.0f;

#pragma unroll
        for (int ks = 0; ks < 4; ks++) {
            uint32_t kh[4][4], kl[4][4];
#pragma unroll
            for (int bt = 0; bt < 4; bt++) {
                uint32_t off = (uint32_t)((bt * 16 + b_row) * AROWB + ks * 32 + b_byte);
                ldm_x4(kh[bt], st + AK_HI + off);
                ldm_x4(kl[bt], st + AK_LO + off);
            }
#pragma unroll
            for (int nt = 0; nt < 8; nt++) {
                uint32_t* BH = &kh[nt >> 1][(nt & 1) * 2];
                uint32_t* BL = &kl[nt >> 1][(nt & 1) * 2];
                mma_bf16(s[nt], qh[ks], BH);
                mma_bf16(s[nt], qh[ks], BL);
                mma_bf16(s[nt], ql[ks], BH);
            }
        }

        const int lr0 = wm + (lane >> 2), lr1 = lr0 + 8;
        const int cbm = (lane & 3) * 2;
        if (kb == qb) {
#pragma unroll
            for (int nt = 0; nt < 8; nt++) {
                int c0 = nt * 8 + cbm;
                if (c0 > lr0)     s[nt][0] = -1e30f;
                if (c0 + 1 > lr0) s[nt][1] = -1e30f;
                if (c0 > lr1)     s[nt][2] = -1e30f;
                if (c0 + 1 > lr1) s[nt][3] = -1e30f;
            }
        }

        float rm0 = -1e30f, rm1 = -1e30f;
#pragma unroll
        for (int nt = 0; nt < 8; nt++) {
            rm0 = fmaxf(rm0, fmaxf(s[nt][0], s[nt][1]));
            rm1 = fmaxf(rm1, fmaxf(s[nt][2], s[nt][3]));
        }
        rm0 = fmaxf(rm0, __shfl_xor_sync(0xffffffffu, rm0, 1));
        rm0 = fmaxf(rm0, __shfl_xor_sync(0xffffffffu, rm0, 2));
        rm1 = fmaxf(rm1, __shfl_xor_sync(0xffffffffu, rm1, 1));
        rm1 = fmaxf(rm1, __shfl_xor_sync(0xffffffffu, rm1, 2));
        float mn0 = fmaxf(mi0, rm0), mn1 = fmaxf(mi1, rm1);
        float al0 = __expf(mi0 - mn0), al1 = __expf(mi1 - mn1);
        float rs0 = 0.0f, rs1 = 0.0f;
#pragma unroll
        for (int nt = 0; nt < 8; nt++) {
            s[nt][0] = __expf(s[nt][0] - mn0);
            s[nt][1] = __expf(s[nt][1] - mn0);
            s[nt][2] = __expf(s[nt][2] - mn1);
            s[nt][3] = __expf(s[nt][3] - mn1);
            rs0 += s[nt][0] + s[nt][1];
            rs1 += s[nt][2] + s[nt][3];
        }
        rs0 += __shfl_xor_sync(0xffffffffu, rs0, 1);
        rs0 += __shfl_xor_sync(0xffffffffu, rs0, 2);
        rs1 += __shfl_xor_sync(0xffffffffu, rs1, 1);
        rs1 += __shfl_xor_sync(0xffffffffu, rs1, 2);
        li0 = li0 * al0 + rs0; li1 = li1 * al1 + rs1;
        mi0 = mn0; mi1 = mn1;
#pragma unroll
        for (int dt = 0; dt < 8; dt++) {
            oacc[dt][0] *= al0; oacc[dt][1] *= al0;
            oacc[dt][2] *= al1; oacc[dt][3] *= al1;
        }

#pragma unroll
        for (int ks = 0; ks < 4; ks++) {
            uint32_t ph[4], pl[4];
            ph[0] = pack_split(s[2 * ks][0],     s[2 * ks][1],     &pl[0]);
            ph[1] = pack_split(s[2 * ks][2],     s[2 * ks][3],     &pl[1]);
            ph[2] = pack_split(s[2 * ks + 1][0], s[2 * ks + 1][1], &pl[2]);
            ph[3] = pack_split(s[2 * ks + 1][2], s[2 * ks + 1][3], &pl[3]);
            uint32_t vh[4][4], vl[4][4];
#pragma unroll
            for (int dp = 0; dp < 4; dp++) {
                uint32_t off = (uint32_t)((ks * 16 + v_row) * AROWB + dp * 32 + v_byte);
                ldm_x4_t(vh[dp], st + AV_HI + off);
                ldm_x4_t(vl[dp], st + AV_LO + off);
            }
#pragma unroll
            for (int dt = 0; dt < 8; dt++) {
                uint32_t* BH = &vh[dt >> 1][(dt & 1) * 2];
                uint32_t* BL = &vl[dt >> 1][(dt & 1) * 2];
                mma_bf16(oacc[dt], ph, BH);
                mma_bf16(oacc[dt], ph, BL);
                mma_bf16(oacc[dt], pl, BH);
            }
        }

        __syncthreads();
        if (kb + 2 <= qb) load_kv(kb + 2, kb & 1);
        CPASYNC_COMMIT();
    }

    float i0 = 1.0f / li0, i1 = 1.0f / li1;
    int r0 = q0 + wm + (lane >> 2);
    int cb = (lane & 3) * 2;
#pragma unroll
    for (int dt = 0; dt < 8; dt++) {
        float2 v0 = make_float2(oacc[dt][0] * i0, oacc[dt][1] * i0);
        float2 v1 = make_float2(oacc[dt][2] * i1, oacc[dt][3] * i1);
        *(float2*)&O[base + (size_t)r0 * D_MODEL + dt * 8 + cb] = v0;
        *(float2*)&O[base + (size_t)(r0 + 8) * D_MODEL + dt * 8 + cb] = v1;
    }
}

// ---------------------------------------------------------------------------
// Launch
// ---------------------------------------------------------------------------
extern "C" void kernel_launch(void* const* d_in, const int* in_sizes, int n_in,
                              void* d_out, int out_size)
{
    const float* x  = (const float*)d_in[0];
    const int*   tp = (const int*)d_in[1];
    const float* W[4] = { (const float*)d_in[2], (const float*)d_in[3],
                          (const float*)d_in[4], (const float*)d_in[5] };
    float* out = (float*)d_out;

    float *gA, *sx, *sa, *sw;
    int8_t *x1, *x0, *a1, *a0, *w1, *w0;
    __nv_bfloat16 *qhi, *qlo, *khi, *klo, *vhi, *vlo;
    float2* cs;
    cudaGetSymbolAddress((void**)&gA, g_A);
    cudaGetSymbolAddress((void**)&x1, g_x1);
    cudaGetSymbolAddress((void**)&x0, g_x0);
    cudaGetSymbolAddress((void**)&a1, g_a1);
    cudaGetSymbolAddress((void**)&a0, g_a0);
    cudaGetSymbolAddress((void**)&w1, g_w1);
    cudaGetSymbolAddress((void**)&w0, g_w0);
    cudaGetSymbolAddress((void**)&sx, g_sx);
    cudaGetSymbolAddress((void**)&sa, g_sa);
    cudaGetSymbolAddress((void**)&sw, g_sw);
    cudaGetSymbolAddress((void**)&qhi, g_qhi);
    cudaGetSymbolAddress((void**)&qlo, g_qlo);
    cudaGetSymbolAddress((void**)&khi, g_khi);
    cudaGetSymbolAddress((void**)&klo, g_klo);
    cudaGetSymbolAddress((void**)&vhi, g_vhi);
    cudaGetSymbolAddress((void**)&vlo, g_vlo);
    cudaGetSymbolAddress((void**)&cs, g_cs);

    const size_t WSZ = (size_t)D_MODEL * D_MODEL;

    // One fused prologue launch: x quant + 4 weight quants + RoPE table.
    prologue<<<1544, 256>>>(x, W[0], W[1], W[2], W[3], tp,
                            (char4*)x1, (char4*)x0, sx,
                            (char4*)w1, (char4*)w0, sw, cs);

    cudaFuncSetAttribute(gemm_qkv, cudaFuncAttributeMaxDynamicSharedMemorySize, ISMEM);
    cudaFuncSetAttribute(gemm_out, cudaFuncAttributeMaxDynamicSharedMemorySize, ISMEM);

    gemm_qkv<<<dim3(D_MODEL / 128, M_TOTAL / 64, 3), 256, ISMEM>>>(
        x1, x0, w1, w0, sx, sw, qhi, qlo, khi, klo, vhi, vlo, cs);

    cudaFuncSetAttribute(attn_mma, cudaFuncAttributeMaxDynamicSharedMemorySize, ATTN_SMEM);
    attn_mma<<<dim3(SEQ / 64, BATCH * NUM_HEADS), 128, ATTN_SMEM>>>(
        qhi, qlo, khi, klo, vhi, vlo, gA);

    quant_rows<<<M_TOTAL / 8, 256>>>(gA, (char4*)a1, (char4*)a0, sa);
    gemm_out<<<dim3(D_MODEL / 128, M_TOTAL / 64), 256, ISMEM>>>(
        a1, a0, w1 + 3 * WSZ, w0 + 3 * WSZ, sa, sw + 3 * D_MODEL, out);
}